// round 14
// baseline (speedup 1.0000x reference)
#include <cuda_runtime.h>
#include <cstdint>

// Problem constants
#define BB  16
#define NN  16384
#define SS  1024
#define CC  128
#define SEM 20

// Cluster FPS config
#define CL   4               // CTAs per cluster (one cluster per batch)
#define T    512             // threads per CTA
#define NLOC (NN / CL)       // 4096 points per CTA
#define PPT  (NLOC / T)      // 8 points per thread
#define NPAIR (PPT / 2)      // 4 packed pairs per thread
#define NW   (T / 32)        // 16 warps

#define A0 (BB * SS * 3)
#define A1 (BB * CC * SS)
#define A2 (BB * SS)

__device__ int g_idx[BB * SS];

// Dynamic smem layout (bytes)
#define OFF_X     0
#define OFF_Y     (NLOC * 4)
#define OFF_Z     (NLOC * 8)
#define OFF_CNT   (NLOC * 12)           // 32 floats
#define OFF_WARP  (OFF_CNT + 128)       // 16 x u64 {score|idx|seq}
#define OFF_WIN   (OFF_WARP + 128)      // 4 u32 {x,y,z,gi}
#define OFF_WFLAG (OFF_WIN + 16)        // u32 flag (+pad)
#define OFF_CAND  (OFF_WFLAG + 16)      // [2 parity][4 slots][24B records]
#define SMEM_BYTES (OFF_CAND + 192)

// ---------------- PTX helpers ----------------
static __device__ __forceinline__ uint32_t smem_u32(const void* p) {
    uint32_t a;
    asm("{ .reg .u64 t; cvta.to.shared.u64 t, %1; cvt.u32.u64 %0, t; }"
        : "=r"(a) : "l"(p));
    return a;
}
static __device__ __forceinline__ uint32_t mapa_u32(uint32_t a, uint32_t rank) {
    uint32_t d;
    asm("mapa.shared::cluster.u32 %0, %1, %2;" : "=r"(d) : "r"(a), "r"(rank));
    return d;
}
static __device__ __forceinline__ void st_cl_u64(uint32_t a, uint64_t v) {
    asm volatile("st.shared::cluster.b64 [%0], %1;" :: "r"(a), "l"(v) : "memory");
}
static __device__ __forceinline__ void st_cl_rel_u64(uint32_t a, uint64_t v) {
    asm volatile("st.release.cluster.shared::cluster.b64 [%0], %1;"
                 :: "r"(a), "l"(v) : "memory");
}
static __device__ __forceinline__ uint32_t ld_acq_cluster_u32(uint32_t a) {
    uint32_t v;
    asm volatile("ld.acquire.cluster.shared::cta.b32 %0, [%1];"
                 : "=r"(v) : "r"(a) : "memory");
    return v;
}
static __device__ __forceinline__ void st_rel_cta_u32(uint32_t a, uint32_t v) {
    asm volatile("st.release.cta.shared::cta.b32 [%0], %1;"
                 :: "r"(a), "r"(v) : "memory");
}
static __device__ __forceinline__ uint32_t ld_acq_cta_u32(uint32_t a) {
    uint32_t v;
    asm volatile("ld.acquire.cta.shared::cta.b32 %0, [%1];"
                 : "=r"(v) : "r"(a) : "memory");
    return v;
}
static __device__ __forceinline__ uint64_t ld_vol_u64(uint32_t a) {
    uint64_t v;
    asm volatile("ld.volatile.shared.b64 %0, [%1];" : "=l"(v) : "r"(a) : "memory");
    return v;
}
static __device__ __forceinline__ void st_vol_u64(uint32_t a, uint64_t v) {
    asm volatile("st.volatile.shared.b64 [%0], %1;" :: "r"(a), "l"(v) : "memory");
}
static __device__ __forceinline__ uint32_t redux_max_u32(uint32_t v) {
    uint32_t o;
    asm volatile("redux.sync.max.u32 %0, %1, 0xffffffff;" : "=r"(o) : "r"(v));
    return o;
}
// Packed f32x2 (per-lane bitwise identical to scalar rn ops)
static __device__ __forceinline__ uint64_t pk2(float lo, float hi) {
    uint64_t r;
    asm("mov.b64 %0, {%1, %2};"
        : "=l"(r) : "r"(__float_as_uint(lo)), "r"(__float_as_uint(hi)));
    return r;
}
static __device__ __forceinline__ void unpk2(uint64_t v, float& lo, float& hi) {
    uint32_t a, c;
    asm("mov.b64 {%0, %1}, %2;" : "=r"(a), "=r"(c) : "l"(v));
    lo = __uint_as_float(a); hi = __uint_as_float(c);
}
static __device__ __forceinline__ uint64_t add2(uint64_t a, uint64_t b) {
    uint64_t o; asm("add.rn.f32x2 %0, %1, %2;" : "=l"(o) : "l"(a), "l"(b)); return o;
}
static __device__ __forceinline__ uint64_t mul2(uint64_t a, uint64_t b) {
    uint64_t o; asm("mul.rn.f32x2 %0, %1, %2;" : "=l"(o) : "l"(a), "l"(b)); return o;
}
static __device__ __forceinline__ uint64_t fma2(uint64_t a, uint64_t b, uint64_t c) {
    uint64_t o; asm("fma.rn.f32x2 %0, %1, %2, %3;" : "=l"(o) : "l"(a), "l"(b), "l"(c)); return o;
}

// ---------------- FPS: one 4-CTA cluster per batch ----------------
__global__ __launch_bounds__(T, 1) __cluster_dims__(CL, 1, 1)
void fps_kernel(const float* __restrict__ xyz, const int* __restrict__ label)
{
    extern __shared__ char smem[];
    float* s_x   = (float*)(smem + OFF_X);
    float* s_y   = (float*)(smem + OFF_Y);
    float* s_z   = (float*)(smem + OFF_Z);
    float* s_cnt = (float*)(smem + OFF_CNT);
    uint32_t* s_win  = (uint32_t*)(smem + OFF_WIN);   // {x,y,z,gi}
    uint32_t* s_cand = (uint32_t*)(smem + OFF_CAND);  // [par][slot][6]: sc,gi,x,y,z,seq

    const int b    = blockIdx.x / CL;
    const int rank = blockIdx.x % CL;
    const int tid  = threadIdx.x;
    const int base = rank * NLOC;
    const float* bx = xyz + (size_t)b * NN * 3;
    const int*   bl = label + (size_t)b * NN;

    const uint32_t warp_a  = smem_u32(smem + OFF_WARP);
    const uint32_t wflag_a = smem_u32(smem + OFF_WFLAG);
    const uint32_t cand_a  = smem_u32(s_cand);

    if (tid < 32) s_cnt[tid] = 0.0f;
    if (tid < 48) s_cand[tid] = 0u;                    // all seq words 0; s >= 1
    if (tid < 32) ((uint32_t*)(smem + OFF_WARP))[tid] = 0u;
    if (tid == 0) *(uint32_t*)(smem + OFF_WFLAG) = 0u;
    __syncthreads();

    // Class histogram over the FULL batch + stage this CTA's coord shard.
    for (int i = tid; i < NN; i += T) atomicAdd(&s_cnt[bl[i]], 1.0f);
    for (int i = tid; i < NLOC; i += T) {
        int g = base + i;
        s_x[i] = bx[3 * g + 0];
        s_y[i] = bx[3 * g + 1];
        s_z[i] = bx[3 * g + 2];
    }
    __syncthreads();

    // Register-resident packed coords/weights. Pair j holds points
    // p0 = tid + (2j)*T, p1 = tid + (2j+1)*T.
    uint64_t px[NPAIR], py[NPAIR], pz[NPAIR], pw[NPAIR];
    float M[PPT];
    #pragma unroll
    for (int j = 0; j < NPAIR; j++) {
        int p0 = tid + (2 * j) * T, p1 = tid + (2 * j + 1) * T;
        px[j] = pk2(s_x[p0], s_x[p1]);
        py[j] = pk2(s_y[p0], s_y[p1]);
        pz[j] = pk2(s_z[p0], s_z[p1]);
        float w0 = s_cnt[bl[base + p0]], w1 = s_cnt[bl[base + p1]];
        pw[j] = pk2(w0, w1);
        M[2 * j]     = 1e10f * w0;      // matches min(1e10,d)*w after iter 1
        M[2 * j + 1] = 1e10f * w1;
    }

    float cx = bx[0], cy = bx[1], cz = bx[2];
    if (rank == 0 && tid == 0) g_idx[b * SS] = 0;

    const int wid = tid >> 5, lane = tid & 31;

    // Remote record destinations: warp-0 lanes 0..2 each serve one peer.
    // Record written into the RECEIVER's buffer at slot index == MY rank.
    uint32_t dst0 = 0, dst1 = 0;
    if (wid == 0 && lane < CL - 1) {
        uint32_t peer = (uint32_t)((rank + 1 + lane) % CL);
        dst0 = mapa_u32(cand_a + (uint32_t)(rank * 24),        peer);
        dst1 = mapa_u32(cand_a + (uint32_t)((CL + rank) * 24), peer);
    }

    // Peers' smem must be initialized before any cross-CTA store.
    asm volatile("barrier.cluster.arrive.aligned;" ::: "memory");
    asm volatile("barrier.cluster.wait.aligned;" ::: "memory");

    for (int s = 1; s < SS; s++) {
        const uint64_t ncx = pk2(-cx, -cx);
        const uint64_t ncy = pk2(-cy, -cy);
        const uint64_t ncz = pk2(-cz, -cz);

        // ---- Phase 1: packed distance + min update; track max score ----
        float best = 0.0f;                       // scores >= 0
        #pragma unroll
        for (int j = 0; j < NPAIR; j++) {
            uint64_t dx = add2(px[j], ncx);      // rn(x - cx) per lane
            uint64_t dy = add2(py[j], ncy);
            uint64_t dz = add2(pz[j], ncz);
            uint64_t t  = mul2(dx, dx);          // XLA-contracted:
            t = fma2(dy, dy, t);                 // fma(dy,dy, dx*dx)
            t = fma2(dz, dz, t);                 // fma(dz,dz, ...)
            uint64_t dw = mul2(t, pw[j]);        // d * w
            float lo, hi; unpk2(dw, lo, hi);
            float m0 = fminf(M[2 * j],     lo);
            float m1 = fminf(M[2 * j + 1], hi);
            M[2 * j] = m0; M[2 * j + 1] = m1;
            best = fmaxf(best, m0);
            best = fmaxf(best, m1);
        }
        // ---- Phase 2: lowest local index attaining this thread's best ----
        int bi = 0x7fffffff;
        #pragma unroll
        for (int k = PPT - 1; k >= 0; k--)
            if (M[k] == best) bi = tid + k * T;

        // ---- Warp reduce (u32 max on non-negative score bits; min idx) ----
        uint32_t sb  = __float_as_uint(best);
        uint32_t smx = redux_max_u32(sb);
        unsigned bio = __reduce_min_sync(0xffffffffu,
                         (sb == smx) ? (unsigned)bi : 0x7fffffffu);
        // Single-word seq-stamped result: {score:32 | idx:12 | seq:10}
        if (lane == 0)
            st_vol_u64(warp_a + (uint32_t)wid * 8,
                       (((uint64_t)smx) << 32)
                       | (((uint64_t)(bio & 0xFFFu)) << 10)
                       | (uint64_t)(s & 1023));

        if (wid == 0) {
            // ---- Coordinator: gather 16 warp results (volatile LDS spin) ----
            uint64_t v = 0;
            bool ok = false;
            do {
                if (lane < NW) v = ld_vol_u64(warp_a + (uint32_t)lane * 8);
                ok = __all_sync(0xffffffffu,
                        (lane >= NW) || (((uint32_t)v & 1023u) == (uint32_t)(s & 1023)));
            } while (!ok);
            uint32_t sc = (lane < NW) ? (uint32_t)(v >> 32) : 0u;
            uint32_t li = (lane < NW) ? (uint32_t)((v >> 10) & 0xFFFu) : 0xffffffffu;
            uint32_t cmax = redux_max_u32(sc);
            uint32_t lmin = __reduce_min_sync(0xffffffffu,
                              (sc == cmax) ? li : 0xffffffffu);
            int   gi  = base + (int)lmin;
            float wxx = s_x[lmin], wyy = s_y[lmin], wzz = s_z[lmin];

            // ---- Send record to 3 peers (lanes 0..2 in parallel) ----
            if (lane < CL - 1) {
                uint32_t dst = (s & 1) ? dst1 : dst0;
                st_cl_u64(dst + 0,  ((uint64_t)(uint32_t)gi << 32) | (uint64_t)cmax);
                st_cl_u64(dst + 8,  ((uint64_t)__float_as_uint(wyy) << 32)
                                   | (uint64_t)__float_as_uint(wxx));
                st_cl_rel_u64(dst + 16, ((uint64_t)(uint32_t)s << 32)
                                   | (uint64_t)__float_as_uint(wzz));
            }

            // ---- Poll 3 peer slots (only THIS warp uses cluster acquires) ----
            uint32_t bufw = (uint32_t)((s & 1) * CL * 6);
            uint32_t Wsc = cmax; int Wgi = gi;
            float Wx = wxx, Wy = wyy, Wz = wzz;
            #pragma unroll
            for (int j = 0; j < CL - 1; j++) {
                uint32_t slot = (uint32_t)((rank + 1 + j) % CL);
                uint32_t wo   = bufw + slot * 6;
                while (ld_acq_cluster_u32(cand_a + (wo + 5) * 4) != (uint32_t)s) { }
                uint32_t psc = s_cand[wo + 0];
                int      pgi = (int)s_cand[wo + 1];
                if (psc > Wsc || (psc == Wsc && pgi < Wgi)) {
                    Wsc = psc; Wgi = pgi;
                    Wx = __uint_as_float(s_cand[wo + 2]);
                    Wy = __uint_as_float(s_cand[wo + 3]);
                    Wz = __uint_as_float(s_cand[wo + 4]);
                }
            }
            // ---- Publish winner to own CTA ----
            if (lane == 0) {
                s_win[0] = __float_as_uint(Wx);
                s_win[1] = __float_as_uint(Wy);
                s_win[2] = __float_as_uint(Wz);
                s_win[3] = (uint32_t)Wgi;
                st_rel_cta_u32(wflag_a, (uint32_t)s);
                if (rank == 0) g_idx[b * SS + s] = Wgi;
            }
            cx = Wx; cy = Wy; cz = Wz;
        } else {
            // ---- Followers: cheap CTA-scope acquire spin, then read winner ----
            while (ld_acq_cta_u32(wflag_a) != (uint32_t)s) { }
            cx = __uint_as_float(s_win[0]);
            cy = __uint_as_float(s_win[1]);
            cz = __uint_as_float(s_win[2]);
        }
    }

    // Keep cluster alive until all remote traffic has retired.
    asm volatile("barrier.cluster.arrive.aligned;" ::: "memory");
    asm volatile("barrier.cluster.wait.aligned;" ::: "memory");
}

// ---------------- Gather ----------------
__global__ void gather_kernel(const float* __restrict__ xyz,
                              const float* __restrict__ feat,
                              const int*   __restrict__ label,
                              float* __restrict__ out)
{
    int i = blockIdx.x * blockDim.x + threadIdx.x;
    const int total = A0 + A1 + A2;
    if (i >= total) return;

    if (i < A0) {
        int b = i / (SS * 3);
        int r = i - b * SS * 3;
        int s = r / 3;
        int d = r - s * 3;
        int id = g_idx[b * SS + s];
        out[i] = xyz[((size_t)b * NN + id) * 3 + d];
    } else if (i < A0 + A1) {
        int j = i - A0;
        int b = j / (CC * SS);
        int r = j - b * CC * SS;
        int c = r / SS;
        int s = r - c * SS;
        int id = g_idx[b * SS + s];
        out[i] = feat[((size_t)b * CC + c) * NN + id];
    } else {
        int j = i - A0 - A1;
        int b = j / SS;
        int s = j - b * SS;
        int id = g_idx[b * SS + s];
        out[i] = (float)label[(size_t)b * NN + id];
    }
}

extern "C" void kernel_launch(void* const* d_in, const int* in_sizes, int n_in,
                              void* d_out, int out_size)
{
    const float* xyz   = (const float*)d_in[0];
    const float* feat  = (const float*)d_in[1];
    const int*   label = (const int*)  d_in[2];
    float*       out   = (float*)d_out;

    cudaFuncSetAttribute(fps_kernel,
                         cudaFuncAttributeMaxDynamicSharedMemorySize,
                         SMEM_BYTES);

    fps_kernel<<<BB * CL, T, SMEM_BYTES>>>(xyz, label);

    const int total = A0 + A1 + A2;
    gather_kernel<<<(total + 255) / 256, 256>>>(xyz, feat, label, out);
}

// round 15
// speedup vs baseline: 1.1647x; 1.1647x over previous
#include <cuda_runtime.h>
#include <cstdint>

// Problem constants
#define BB  16
#define NN  16384
#define SS  1024
#define CC  128
#define SEM 20

// Cluster FPS config
#define CL   4               // CTAs per cluster (one cluster per batch)
#define T    512             // threads per CTA
#define NLOC (NN / CL)       // 4096 points per CTA
#define PPT  (NLOC / T)      // 8 points per thread
#define NPAIR (PPT / 2)      // 4 packed pairs per thread
#define NW   (T / 32)        // 16 warps

#define A0 (BB * SS * 3)
#define A1 (BB * CC * SS)
#define A2 (BB * SS)

__device__ int g_idx[BB * SS];

// Dynamic smem layout (bytes)
#define OFF_X    0
#define OFF_Y    (NLOC * 4)
#define OFF_Z    (NLOC * 8)
#define OFF_CNT  (NLOC * 12)            // 32 floats
#define OFF_WARP (OFF_CNT + 128)        // 2 bufs x 16 x u64 {score, idx}
#define OFF_CAND (OFF_WARP + 256)       // [2 parity][4 slots][24B records]
#define SMEM_BYTES (OFF_CAND + 192)

// ---------------- PTX helpers ----------------
static __device__ __forceinline__ uint32_t smem_u32(const void* p) {
    uint32_t a;
    asm("{ .reg .u64 t; cvta.to.shared.u64 t, %1; cvt.u32.u64 %0, t; }"
        : "=r"(a) : "l"(p));
    return a;
}
static __device__ __forceinline__ uint32_t mapa_u32(uint32_t a, uint32_t rank) {
    uint32_t d;
    asm("mapa.shared::cluster.u32 %0, %1, %2;" : "=r"(d) : "r"(a), "r"(rank));
    return d;
}
static __device__ __forceinline__ void st_cl_u64(uint32_t a, uint64_t v) {
    asm volatile("st.shared::cluster.b64 [%0], %1;" :: "r"(a), "l"(v) : "memory");
}
static __device__ __forceinline__ void st_cl_rel_u64(uint32_t a, uint64_t v) {
    asm volatile("st.release.cluster.shared::cluster.b64 [%0], %1;"
                 :: "r"(a), "l"(v) : "memory");
}
static __device__ __forceinline__ uint32_t ld_vol_u32(uint32_t a) {
    uint32_t v;
    asm volatile("ld.volatile.shared.b32 %0, [%1];" : "=r"(v) : "r"(a) : "memory");
    return v;
}
static __device__ __forceinline__ void fence_acq_rel_cluster() {
    asm volatile("fence.acq_rel.cluster;" ::: "memory");
}
static __device__ __forceinline__ uint32_t redux_max_u32(uint32_t v) {
    uint32_t o;
    asm volatile("redux.sync.max.u32 %0, %1, 0xffffffff;" : "=r"(o) : "r"(v));
    return o;
}
// Packed f32x2 (per-lane bitwise identical to scalar rn ops)
static __device__ __forceinline__ uint64_t pk2(float lo, float hi) {
    uint64_t r;
    asm("mov.b64 %0, {%1, %2};"
        : "=l"(r) : "r"(__float_as_uint(lo)), "r"(__float_as_uint(hi)));
    return r;
}
static __device__ __forceinline__ void unpk2(uint64_t v, float& lo, float& hi) {
    uint32_t a, c;
    asm("mov.b64 {%0, %1}, %2;" : "=r"(a), "=r"(c) : "l"(v));
    lo = __uint_as_float(a); hi = __uint_as_float(c);
}
static __device__ __forceinline__ uint64_t add2(uint64_t a, uint64_t b) {
    uint64_t o; asm("add.rn.f32x2 %0, %1, %2;" : "=l"(o) : "l"(a), "l"(b)); return o;
}
static __device__ __forceinline__ uint64_t mul2(uint64_t a, uint64_t b) {
    uint64_t o; asm("mul.rn.f32x2 %0, %1, %2;" : "=l"(o) : "l"(a), "l"(b)); return o;
}
static __device__ __forceinline__ uint64_t fma2(uint64_t a, uint64_t b, uint64_t c) {
    uint64_t o; asm("fma.rn.f32x2 %0, %1, %2, %3;" : "=l"(o) : "l"(a), "l"(b), "l"(c)); return o;
}

// ---------------- FPS: one 4-CTA cluster per batch ----------------
__global__ __launch_bounds__(T, 1) __cluster_dims__(CL, 1, 1)
void fps_kernel(const float* __restrict__ xyz, const int* __restrict__ label)
{
    extern __shared__ char smem[];
    float* s_x   = (float*)(smem + OFF_X);
    float* s_y   = (float*)(smem + OFF_Y);
    float* s_z   = (float*)(smem + OFF_Z);
    float* s_cnt = (float*)(smem + OFF_CNT);
    unsigned long long* s_warp = (unsigned long long*)(smem + OFF_WARP);
    uint32_t* s_cand = (uint32_t*)(smem + OFF_CAND);  // [par][slot][6]: sc,gi,x,y,z,seq

    const int b    = blockIdx.x / CL;
    const int rank = blockIdx.x % CL;
    const int tid  = threadIdx.x;
    const int base = rank * NLOC;
    const float* bx = xyz + (size_t)b * NN * 3;
    const int*   bl = label + (size_t)b * NN;

    const uint32_t cand_a = smem_u32(s_cand);

    if (tid < 32) s_cnt[tid] = 0.0f;
    if (tid < 48) s_cand[tid] = 0u;      // all seq words 0; s >= 1
    __syncthreads();

    // Class histogram over the FULL batch + stage this CTA's coord shard.
    for (int i = tid; i < NN; i += T) atomicAdd(&s_cnt[bl[i]], 1.0f);
    for (int i = tid; i < NLOC; i += T) {
        int g = base + i;
        s_x[i] = bx[3 * g + 0];
        s_y[i] = bx[3 * g + 1];
        s_z[i] = bx[3 * g + 2];
    }
    __syncthreads();

    // Register-resident packed coords/weights. Pair j holds points
    // p0 = tid + (2j)*T, p1 = tid + (2j+1)*T.
    uint64_t px[NPAIR], py[NPAIR], pz[NPAIR], pw[NPAIR];
    float M[PPT];
    #pragma unroll
    for (int j = 0; j < NPAIR; j++) {
        int p0 = tid + (2 * j) * T, p1 = tid + (2 * j + 1) * T;
        px[j] = pk2(s_x[p0], s_x[p1]);
        py[j] = pk2(s_y[p0], s_y[p1]);
        pz[j] = pk2(s_z[p0], s_z[p1]);
        float w0 = s_cnt[bl[base + p0]], w1 = s_cnt[bl[base + p1]];
        pw[j] = pk2(w0, w1);
        M[2 * j]     = 1e10f * w0;      // matches min(1e10,d)*w after iter 1
        M[2 * j + 1] = 1e10f * w1;
    }

    float cx = bx[0], cy = bx[1], cz = bx[2];
    if (rank == 0 && tid == 0) g_idx[b * SS] = 0;

    const int wid = tid >> 5, lane = tid & 31;

    // Remote record destinations: warp-0 lanes 0..2 each serve one peer.
    // Record written into the RECEIVER's buffer at slot index == MY rank.
    uint32_t dst0 = 0, dst1 = 0;
    if (wid == 0 && lane < CL - 1) {
        uint32_t peer = (uint32_t)((rank + 1 + lane) % CL);
        dst0 = mapa_u32(cand_a + (uint32_t)(rank * 24),            peer);
        dst1 = mapa_u32(cand_a + (uint32_t)((CL + rank) * 24),     peer);
    }

    // Each lane's poll assignment (lanes 0..2 poll distinct slots).
    const uint32_t myslot = (uint32_t)((rank + 1 + lane) % CL);

    // Peers' smem must be initialized before any cross-CTA store.
    asm volatile("barrier.cluster.arrive.aligned;" ::: "memory");
    asm volatile("barrier.cluster.wait.aligned;" ::: "memory");

    for (int s = 1; s < SS; s++) {
        const uint64_t ncx = pk2(-cx, -cx);
        const uint64_t ncy = pk2(-cy, -cy);
        const uint64_t ncz = pk2(-cz, -cz);

        // ---- Phase 1: packed distance + min update; track max score ----
        float best = 0.0f;                       // scores >= 0
        #pragma unroll
        for (int j = 0; j < NPAIR; j++) {
            uint64_t dx = add2(px[j], ncx);      // rn(x - cx) per lane
            uint64_t dy = add2(py[j], ncy);
            uint64_t dz = add2(pz[j], ncz);
            uint64_t t  = mul2(dx, dx);          // XLA-contracted:
            t = fma2(dy, dy, t);                 // fma(dy,dy, dx*dx)
            t = fma2(dz, dz, t);                 // fma(dz,dz, ...)
            uint64_t dw = mul2(t, pw[j]);        // d * w
            float lo, hi; unpk2(dw, lo, hi);
            float m0 = fminf(M[2 * j],     lo);
            float m1 = fminf(M[2 * j + 1], hi);
            M[2 * j] = m0; M[2 * j + 1] = m1;
            best = fmaxf(best, m0);
            best = fmaxf(best, m1);
        }
        // ---- Phase 2: lowest local index attaining this thread's best ----
        int bi = 0x7fffffff;
        #pragma unroll
        for (int k = PPT - 1; k >= 0; k--)
            if (M[k] == best) bi = tid + k * T;

        // ---- Warp reduce (u32 max on non-negative score bits; min idx) ----
        uint32_t sb  = __float_as_uint(best);
        uint32_t smx = redux_max_u32(sb);
        unsigned bio = __reduce_min_sync(0xffffffffu,
                         (sb == smx) ? (unsigned)bi : 0x7fffffffu);
        unsigned long long* swb = &s_warp[(s & 1) * NW];   // parity buffered
        if (lane == 0)
            swb[wid] = (((unsigned long long)smx) << 32) | (unsigned long long)bio;
        __syncthreads();   // the ONLY barrier in the iteration

        // ---- EVERY warp redundantly: CTA reduce; warp0 lanes 0-2 send ----
        unsigned long long pkd = (lane < NW) ? swb[lane] : 0ULL;
        uint32_t sc = (uint32_t)(pkd >> 32);
        uint32_t li = (lane < NW) ? (uint32_t)pkd : 0x7fffffffu;
        uint32_t cmax = redux_max_u32(sc);
        uint32_t lmin = __reduce_min_sync(0xffffffffu,
                          (sc == cmax) ? li : 0x7fffffffu);
        int   gi  = base + (int)lmin;
        float wxx = s_x[lmin], wyy = s_y[lmin], wzz = s_z[lmin];

        if (wid == 0 && lane < CL - 1) {
            // 3 lanes send in parallel: [sc, gi] [x, y] [z, seq(release)]
            uint32_t dst = (s & 1) ? dst1 : dst0;
            st_cl_u64(dst + 0,  ((uint64_t)(uint32_t)gi << 32) | (uint64_t)cmax);
            st_cl_u64(dst + 8,  ((uint64_t)__float_as_uint(wyy) << 32)
                               | (uint64_t)__float_as_uint(wxx));
            st_cl_rel_u64(dst + 16, ((uint64_t)(uint32_t)s << 32)
                               | (uint64_t)__float_as_uint(wzz));
        }

        // ---- Poll 3 peer slots with cheap volatile LDS (lanes 0-2 parallel),
        //      then ONE acquire fence per warp; reduce 4 candidates ----
        uint32_t bufw = (uint32_t)((s & 1) * CL * 6);      // word offset of parity buf
        {
            uint32_t seq_a = cand_a + (bufw + myslot * 6 + 5) * 4;
            bool ready = (lane >= CL - 1);
            do {
                if (!ready) ready = (ld_vol_u32(seq_a) == (uint32_t)s);
            } while (!__all_sync(0xffffffffu, ready));
        }
        fence_acq_rel_cluster();   // orders peer record data reads below

        uint32_t Wsc = cmax; int Wgi = gi;
        float Wx = wxx, Wy = wyy, Wz = wzz;
        #pragma unroll
        for (int j = 0; j < CL - 1; j++) {
            uint32_t slot = (uint32_t)((rank + 1 + j) % CL);
            uint32_t wo   = bufw + slot * 6;
            uint32_t psc = s_cand[wo + 0];
            int      pgi = (int)s_cand[wo + 1];
            if (psc > Wsc || (psc == Wsc && pgi < Wgi)) {
                Wsc = psc; Wgi = pgi;
                Wx = __uint_as_float(s_cand[wo + 2]);
                Wy = __uint_as_float(s_cand[wo + 3]);
                Wz = __uint_as_float(s_cand[wo + 4]);
            }
        }
        cx = Wx; cy = Wy; cz = Wz;
        if (rank == 0 && wid == 0 && lane == 0) g_idx[b * SS + s] = Wgi;
    }

    // Keep cluster alive until all remote traffic has retired.
    asm volatile("barrier.cluster.arrive.aligned;" ::: "memory");
    asm volatile("barrier.cluster.wait.aligned;" ::: "memory");
}

// ---------------- Gather ----------------
__global__ void gather_kernel(const float* __restrict__ xyz,
                              const float* __restrict__ feat,
                              const int*   __restrict__ label,
                              float* __restrict__ out)
{
    int i = blockIdx.x * blockDim.x + threadIdx.x;
    const int total = A0 + A1 + A2;
    if (i >= total) return;

    if (i < A0) {
        int b = i / (SS * 3);
        int r = i - b * SS * 3;
        int s = r / 3;
        int d = r - s * 3;
        int id = g_idx[b * SS + s];
        out[i] = xyz[((size_t)b * NN + id) * 3 + d];
    } else if (i < A0 + A1) {
        int j = i - A0;
        int b = j / (CC * SS);
        int r = j - b * CC * SS;
        int c = r / SS;
        int s = r - c * SS;
        int id = g_idx[b * SS + s];
        out[i] = feat[((size_t)b * CC + c) * NN + id];
    } else {
        int j = i - A0 - A1;
        int b = j / SS;
        int s = j - b * SS;
        int id = g_idx[b * SS + s];
        out[i] = (float)label[(size_t)b * NN + id];
    }
}

extern "C" void kernel_launch(void* const* d_in, const int* in_sizes, int n_in,
                              void* d_out, int out_size)
{
    const float* xyz   = (const float*)d_in[0];
    const float* feat  = (const float*)d_in[1];
    const int*   label = (const int*)  d_in[2];
    float*       out   = (float*)d_out;

    cudaFuncSetAttribute(fps_kernel,
                         cudaFuncAttributeMaxDynamicSharedMemorySize,
                         SMEM_BYTES);

    fps_kernel<<<BB * CL, T, SMEM_BYTES>>>(xyz, label);

    const int total = A0 + A1 + A2;
    gather_kernel<<<(total + 255) / 256, 256>>>(xyz, feat, label, out);
}